// round 16
// baseline (speedup 1.0000x reference)
#include <cuda_runtime.h>
#include <math.h>
#include <stdint.h>

#define BB 64
#define NN 512
#define DD 128
#define MM 128
#define NEG_INF -1e9f

// Scratch (device globals)
__device__ float g_M[DD * DD];         // M[e][d], pre-rounded to tf32
__device__ float g_part[BB * 8 * 128]; // per-(batch,chunk) partial masked sums
__device__ int   g_ccnt[BB * 8];       // per-chunk active counts
__device__ float g_s[BB * NN];         // s_i = a_i^T M a_i (active rows only)
__device__ float g_G[BB * DD];         // per-batch G vector
__device__ float g_C[BB];              // per-batch scalar
__device__ int   g_arrive[BB];         // per-batch arrival counters (self-resetting)

__device__ __forceinline__ float warp_sum(float v) {
#pragma unroll
    for (int o = 16; o; o >>= 1) v += __shfl_xor_sync(0xffffffffu, v, o);
    return v;
}
__device__ __forceinline__ float warp_max(float v) {
#pragma unroll
    for (int o = 16; o; o >>= 1) v = fmaxf(v, __shfl_xor_sync(0xffffffffu, v, o));
    return v;
}
__device__ __forceinline__ float dot4(float4 a, float4 b) {
    return a.x * b.x + a.y * b.y + a.z * b.z + a.w * b.w;
}
__device__ __forceinline__ float tf32_rna(float f) {
    uint32_t u;
    asm("cvt.rna.tf32.f32 %0, %1;" : "=r"(u) : "f"(f));
    return __uint_as_float(u);
}
__device__ __forceinline__ uint32_t tf32_bits(float f) {
    uint32_t u;
    asm("cvt.rna.tf32.f32 %0, %1;" : "=r"(u) : "f"(f));
    return u;
}
__device__ __forceinline__ void mma_tf32(float* c, const uint32_t* a,
                                         uint32_t b0, uint32_t b1) {
    asm("mma.sync.aligned.m16n8k8.row.col.f32.tf32.tf32.f32 "
        "{%0,%1,%2,%3}, {%4,%5,%6,%7}, {%8,%9}, {%0,%1,%2,%3};"
        : "+f"(c[0]), "+f"(c[1]), "+f"(c[2]), "+f"(c[3])
        : "r"(a[0]), "r"(a[1]), "r"(a[2]), "r"(a[3]), "r"(b0), "r"(b1));
}

// ---------------------------------------------------------------------------
// K0: M[e][d] = Wk row e . Wq row d, stored tf32-rounded.
// ---------------------------------------------------------------------------
__global__ __launch_bounds__(128) void mcol_kernel(
    const float* __restrict__ Wq, const float* __restrict__ Wk)
{
    __shared__ float4 wk[32];
    const int e = blockIdx.x;
    const int d = threadIdx.x;
    if (d < 32) wk[d] = ((const float4*)Wk)[e * 32 + d];
    __syncthreads();

    const float4* wq = (const float4*)(Wq + d * MM);
    float acc = 0.f;
#pragma unroll
    for (int m = 0; m < 32; m++) {
        float4 q = wq[m];
        float4 k = wk[m];
        acc = fmaf(q.x, k.x, acc);
        acc = fmaf(q.y, k.y, acc);
        acc = fmaf(q.z, k.z, acc);
        acc = fmaf(q.w, k.w, acc);
    }
    g_M[e * DD + d] = tf32_rna(acc);
}

// ---------------------------------------------------------------------------
// K1: grid 512 (8 chunks per batch), 256 threads, ~41KB smem -> 3 blocks/SM.
// Stages A only; M read directly through L1 (64KB, shared by all blocks).
// tf32 MMA quadratic form; last block per batch computes stats inline.
// smem byte offsets (all float4 regions 16B-aligned):
//   A     @0       34816
//   part  @34816    4096
//   asum  @38912     512
//   qs    @39424     512
//   mask  @39936     256
//   loc   @40192     256
//   sS    @40448     512
//   cnt   @40960       4
//   last  @40964       4
// ---------------------------------------------------------------------------
#define K1_SMEM 40968
#define MST 34   // staged row stride in float4
#define MSTF 136 // staged row stride in floats

__global__ __launch_bounds__(256, 3) void quad_kernel(
    const float* __restrict__ A, const float* __restrict__ mask,
    const float* __restrict__ Wq, const float* __restrict__ Wk,
    const float* __restrict__ bq, const float* __restrict__ bk)
{
    extern __shared__ char smem[];
    float*  sAf   = (float*)smem;
    float4* sA4   = (float4*)smem;
    float*  sPart = (float*)(smem + 34816);
    float*  asum  = (float*)(smem + 38912);
    float*  qs    = (float*)(smem + 39424);
    float*  sMask = (float*)(smem + 39936);
    int*    sLoc  = (int*)(smem + 40192);
    float*  sS    = (float*)(smem + 40448);
    int*    sCnt  = (int*)(smem + 40960);
    int*    sLast = (int*)(smem + 40964);

    const int warp = threadIdx.x >> 5, lane = threadIdx.x & 31, tid = threadIdx.x;
    const int b = blockIdx.x >> 3;
    const int c = blockIdx.x & 7;
    const int r0 = c * 64;
    const size_t base = (size_t)b * NN;
    const float4* A4 = (const float4*)A;
    const float4* Wq4 = (const float4*)Wq;
    const float4* Wk4 = (const float4*)Wk;

    // ---- stage A rows, mask; init sLoc ----
#pragma unroll 2
    for (int idx = tid; idx < 2048; idx += 256) {
        int r = idx >> 5, col = idx & 31;
        sA4[r * MST + col] = A4[(base + r0 + r) * 32 + col];
    }
    if (tid < 64) { sMask[tid] = mask[base + r0 + tid]; sLoc[tid] = -1; }
    __syncthreads();

    // ---- masked partial sums (warp w -> rows w*8..w*8+7) ----
    {
        float4 acc = make_float4(0.f, 0.f, 0.f, 0.f);
#pragma unroll
        for (int j = 0; j < 8; j++) {
            int r = warp * 8 + j;
            float m = sMask[r];
            float4 a = sA4[r * MST + lane];
            acc.x = fmaf(m, a.x, acc.x);
            acc.y = fmaf(m, a.y, acc.y);
            acc.z = fmaf(m, a.z, acc.z);
            acc.w = fmaf(m, a.w, acc.w);
        }
        ((float4*)(sPart + warp * 128))[lane] = acc;
    }

    // ---- chunk compaction (warp 0) ----
    if (warp == 0) {
        float m0 = sMask[lane];
        float m1 = sMask[32 + lane];
        unsigned b0 = __ballot_sync(0xffffffffu, m0 > 0.f);
        unsigned b1 = __ballot_sync(0xffffffffu, m1 > 0.f);
        int c0 = __popc(b0);
        int pre0 = __popc(b0 & ((1u << lane) - 1u));
        int pre1 = __popc(b1 & ((1u << lane) - 1u));
        if (m0 > 0.f) sLoc[pre0] = lane;
        if (m1 > 0.f) sLoc[c0 + pre1] = 32 + lane;
        if (lane == 0) {
            int tot = c0 + __popc(b1);
            g_ccnt[b * 8 + c] = tot;
            *sCnt = tot;
        }
    }
    __syncthreads();

    // ---- reduce partials to global ----
    if (tid < 128) {
        float s = 0.f;
#pragma unroll
        for (int w = 0; w < 8; w++) s += sPart[w * 128 + tid];
        g_part[((size_t)b * 8 + c) * 128 + tid] = s;
    }

    // ---- tf32 tensor-core quadratic form; M read through L1 ----
    {
        const int cnt = *sCnt;
        const int rg = warp & 3;    // 16-slot compacted row group
        const int dh = warp >> 2;   // d half (64 cols)
        const int g  = lane >> 2;   // mma group id
        const int tg = lane & 3;    // mma thread-in-group

        if (rg * 16 < cnt) {
            const int slot0 = rg * 16 + g;
            const int slot1 = slot0 + 8;
            const int loc0 = sLoc[slot0];
            const int loc1 = sLoc[slot1];
            const int l0 = (loc0 >= 0) ? loc0 : 0;
            const int l1 = (loc1 >= 0) ? loc1 : 0;

            float acc[8][4];
#pragma unroll
            for (int t = 0; t < 8; t++)
#pragma unroll
                for (int j = 0; j < 4; j++) acc[t][j] = 0.f;

#pragma unroll
            for (int k = 0; k < 16; k++) {
                const int e0 = k * 8;
                uint32_t ah[4];
                ah[0] = tf32_bits(sAf[l0 * MSTF + e0 + tg]);
                ah[1] = tf32_bits(sAf[l1 * MSTF + e0 + tg]);
                ah[2] = tf32_bits(sAf[l0 * MSTF + e0 + tg + 4]);
                ah[3] = tf32_bits(sAf[l1 * MSTF + e0 + tg + 4]);
                const float* Mr0 = g_M + (e0 + tg) * DD;
                const float* Mr1 = g_M + (e0 + tg + 4) * DD;
#pragma unroll
                for (int t = 0; t < 8; t++) {
                    const int n0 = dh * 64 + t * 8;
                    uint32_t b0 = __float_as_uint(__ldg(Mr0 + n0 + g));
                    uint32_t b1 = __float_as_uint(__ldg(Mr1 + n0 + g));
                    mma_tf32(acc[t], ah, b0, b1);
                }
            }

            // s partials: dot Y rows with fp32 A rows
            float p0 = 0.f, p1 = 0.f;
#pragma unroll
            for (int t = 0; t < 8; t++) {
                const int col = dh * 64 + t * 8 + tg * 2;
                float2 x0 = *(const float2*)&sAf[l0 * MSTF + col];
                float2 x1 = *(const float2*)&sAf[l1 * MSTF + col];
                p0 += acc[t][0] * x0.x + acc[t][1] * x0.y;
                p1 += acc[t][2] * x1.x + acc[t][3] * x1.y;
            }
            p0 += __shfl_xor_sync(0xffffffffu, p0, 1);
            p0 += __shfl_xor_sync(0xffffffffu, p0, 2);
            p1 += __shfl_xor_sync(0xffffffffu, p1, 1);
            p1 += __shfl_xor_sync(0xffffffffu, p1, 2);
            if (tg == 0) {
                sS[dh * 64 + slot0] = p0;
                sS[dh * 64 + slot1] = p1;
            }
        }
    }
    __syncthreads();

    if (tid < 64) {
        int loc = sLoc[tid];
        if (loc >= 0) g_s[base + r0 + loc] = sS[tid] + sS[64 + tid];
    }

    // ---- last-block-done: per-batch stats ----
    __threadfence();
    __syncthreads();
    if (tid == 0) {
        int old = atomicAdd(&g_arrive[b], 1);
        *sLast = (old == 7) ? 1 : 0;
    }
    __syncthreads();
    if (*sLast) {
        int cnt = 0;
#pragma unroll
        for (int cc = 0; cc < 8; cc++) cnt += g_ccnt[b * 8 + cc];

        if (tid < 128) {
            float s = 0.f;
#pragma unroll
            for (int cc = 0; cc < 8; cc++) s += g_part[((size_t)b * 8 + cc) * 128 + tid];
            asum[tid] = s;
        }
        __syncthreads();

        if (tid < 128) {
            float q = (float)cnt * bq[tid];
#pragma unroll 8
            for (int d = 0; d < DD; d++) q = fmaf(asum[d], Wq[d * MM + tid], q);
            qs[tid] = q;
        }
        __syncthreads();

        if (warp == 0) {
            float cv = 0.f;
            for (int m = lane; m < MM; m += 32) cv = fmaf(bk[m], qs[m] - bq[m], cv);
            cv = warp_sum(cv);
            if (lane == 0) g_C[b] = cv;
        }

        {
            float4 qs4 = ((const float4*)qs)[lane];
            float4 bk4 = ((const float4*)bk)[lane];
#pragma unroll
            for (int d = warp; d < DD; d += 8) {
                float p = dot4(Wk4[d * 32 + lane], qs4) - dot4(Wq4[d * 32 + lane], bk4);
                p = warp_sum(p);
                if (lane == 0) g_G[b * DD + d] = p;
            }
        }
        if (tid == 0) atomicExch(&g_arrive[b], 0);   // reset for next replay
    }
}

// ---------------------------------------------------------------------------
// K2: per batch (1024 threads): agg = a.G - s + C (masked) -> normalize ->
//     softmax -> attn out; context = wsum@Wk + bk.
// ---------------------------------------------------------------------------
__global__ __launch_bounds__(1024) void softmax_ctx_kernel(
    const float* __restrict__ A, const float* __restrict__ mask,
    const float* __restrict__ Wk, const float* __restrict__ bk,
    float* __restrict__ out)
{
    const int b = blockIdx.x;
    const int warp = threadIdx.x >> 5, lane = threadIdx.x & 31, tid = threadIdx.x;
    const size_t base = (size_t)b * NN;
    const float4* A4 = (const float4*)A;

    __shared__ float sc[NN];
    __shared__ float sRed[32];
    __shared__ float sW[32][128];
    __shared__ float wsum[128];

    // pass 1: agg from linear term + precomputed quadratic term
    {
        float4 G4 = ((const float4*)(g_G + b * DD))[lane];
        const float C = g_C[b];
#pragma unroll
        for (int i = warp; i < NN; i += 32) {
            float m = mask[base + i];
            float4 a = A4[(base + i) * 32 + lane];
            float lin = dot4(a, G4);
            lin = warp_sum(lin);
            float s = g_s[base + i];
            if (lane == 0) sc[i] = (m > 0.f) ? (lin - s + C) : 0.f;
        }
    }
    __syncthreads();

    // sum of squares
    float ss = 0.f;
    for (int i = tid; i < NN; i += 1024) { float v = sc[i]; ss = fmaf(v, v, ss); }
    ss = warp_sum(ss);
    if (lane == 0) sRed[warp] = ss;
    __syncthreads();
    float tot = 0.f;
#pragma unroll
    for (int w = 0; w < 32; w++) tot += sRed[w];
    float inv = rsqrtf(tot);

    // scores + max
    float mx = -INFINITY;
    for (int i = tid; i < NN; i += 1024) {
        float m = mask[base + i];
        float s = (m > 0.f) ? sc[i] * inv : NEG_INF;
        sc[i] = s;
        mx = fmaxf(mx, s);
    }
    mx = warp_max(mx);
    __syncthreads();
    if (lane == 0) sRed[warp] = mx;
    __syncthreads();
    float M = -INFINITY;
#pragma unroll
    for (int w = 0; w < 32; w++) M = fmaxf(M, sRed[w]);

    // exp & sum
    float es = 0.f;
    for (int i = tid; i < NN; i += 1024) {
        float e = __expf(sc[i] - M);
        sc[i] = e;
        es += e;
    }
    es = warp_sum(es);
    __syncthreads();
    if (lane == 0) sRed[warp] = es;
    __syncthreads();
    float S = 0.f;
#pragma unroll
    for (int w = 0; w < 32; w++) S += sRed[w];
    float invS = 1.0f / S;

    // attn out
    for (int i = tid; i < NN; i += 1024) {
        float at = sc[i] * invS;
        sc[i] = at;
        out[base + i] = at;
    }
    __syncthreads();

    // wsum[d] = sum_i attn_i * A_i[d]
    float4 wacc = make_float4(0.f, 0.f, 0.f, 0.f);
#pragma unroll
    for (int i = warp; i < NN; i += 32) {
        float at = sc[i];
        float4 a = A4[(base + i) * 32 + lane];
        wacc.x = fmaf(at, a.x, wacc.x);
        wacc.y = fmaf(at, a.y, wacc.y);
        wacc.z = fmaf(at, a.z, wacc.z);
        wacc.w = fmaf(at, a.w, wacc.w);
    }
    ((float4*)sW[warp])[lane] = wacc;
    __syncthreads();
    if (tid < 128) {
        float s = 0.f;
#pragma unroll
        for (int w = 0; w < 32; w++) s += sW[w][tid];
        wsum[tid] = s;
    }
    __syncthreads();

    if (tid < 128) {
        float c = bk[tid];
#pragma unroll 8
        for (int d = 0; d < DD; d++) c = fmaf(wsum[d], Wk[d * MM + tid], c);
        out[(size_t)BB * NN + (size_t)b * MM + tid] = c;
    }
}

extern "C" void kernel_launch(void* const* d_in, const int* in_sizes, int n_in,
                              void* d_out, int out_size)
{
    const float* A    = (const float*)d_in[0];
    const float* mask = (const float*)d_in[1];
    const float* Wq   = (const float*)d_in[2];
    const float* bq   = (const float*)d_in[3];
    const float* Wk   = (const float*)d_in[4];
    const float* bk   = (const float*)d_in[5];
    float* out = (float*)d_out;

    cudaFuncSetAttribute(quad_kernel,
                         cudaFuncAttributeMaxDynamicSharedMemorySize, K1_SMEM);

    mcol_kernel<<<128, 128>>>(Wq, Wk);
    quad_kernel<<<BB * 8, 256, K1_SMEM>>>(A, mask, Wq, Wk, bq, bk);
    softmax_ctx_kernel<<<BB, 1024>>>(A, mask, Wk, bk, out);
}

// round 17
// speedup vs baseline: 1.2043x; 1.2043x over previous
#include <cuda_runtime.h>
#include <math.h>
#include <stdint.h>

#define BB 64
#define NN 512
#define DD 128
#define MM 128
#define NEG_INF -1e9f

// Scratch (device globals)
__device__ float g_M[DD * DD];         // M[e][d], pre-rounded to tf32
__device__ float g_part[BB * 8 * 128]; // per-(batch,chunk) partial masked sums
__device__ int   g_ccnt[BB * 8];       // per-chunk active counts
__device__ float g_s[BB * NN];         // s_i = a_i^T M a_i (active rows only)
__device__ float g_G[BB * DD];         // per-batch G vector
__device__ float g_C[BB];              // per-batch scalar
__device__ int   g_arrive[BB];         // per-batch arrival counters (self-resetting)

__device__ __forceinline__ float warp_sum(float v) {
#pragma unroll
    for (int o = 16; o; o >>= 1) v += __shfl_xor_sync(0xffffffffu, v, o);
    return v;
}
__device__ __forceinline__ float dot4(float4 a, float4 b) {
    return a.x * b.x + a.y * b.y + a.z * b.z + a.w * b.w;
}
__device__ __forceinline__ float tf32_rna(float f) {
    uint32_t u;
    asm("cvt.rna.tf32.f32 %0, %1;" : "=r"(u) : "f"(f));
    return __uint_as_float(u);
}
__device__ __forceinline__ uint32_t tf32_bits(float f) {
    uint32_t u;
    asm("cvt.rna.tf32.f32 %0, %1;" : "=r"(u) : "f"(f));
    return u;
}
__device__ __forceinline__ void mma_tf32(float* c, const uint32_t* a,
                                         uint32_t b0, uint32_t b1) {
    asm("mma.sync.aligned.m16n8k8.row.col.f32.tf32.tf32.f32 "
        "{%0,%1,%2,%3}, {%4,%5,%6,%7}, {%8,%9}, {%0,%1,%2,%3};"
        : "+f"(c[0]), "+f"(c[1]), "+f"(c[2]), "+f"(c[3])
        : "r"(a[0]), "r"(a[1]), "r"(a[2]), "r"(a[3]), "r"(b0), "r"(b1));
}

// ---------------------------------------------------------------------------
// K0 v3: M[e][d] = Wk row e . Wq row d, tf32-rounded.
// 256 threads: dot split across thread pairs (64-deep FMA chain each).
// ---------------------------------------------------------------------------
__global__ __launch_bounds__(256) void mcol_kernel(
    const float* __restrict__ Wq, const float* __restrict__ Wk)
{
    __shared__ float4 wk[32];
    __shared__ float sHalf[256];
    const int e = blockIdx.x;
    const int tid = threadIdx.x;
    const int d = tid & 127;
    const int h = tid >> 7;          // which half of the k-dim
    if (tid < 32) wk[tid] = ((const float4*)Wk)[e * 32 + tid];
    __syncthreads();

    const float4* wq = (const float4*)(Wq + d * MM);
    float acc = 0.f;
#pragma unroll
    for (int m = h * 16; m < h * 16 + 16; m++) {
        float4 q = wq[m];
        float4 k = wk[m];
        acc = fmaf(q.x, k.x, acc);
        acc = fmaf(q.y, k.y, acc);
        acc = fmaf(q.z, k.z, acc);
        acc = fmaf(q.w, k.w, acc);
    }
    sHalf[tid] = acc;
    __syncthreads();
    if (tid < 128) g_M[e * DD + tid] = tf32_rna(sHalf[tid] + sHalf[tid + 128]);
}

// ---------------------------------------------------------------------------
// K1: identical to the 41.4us version (R14). grid 512, 256 thr, 110.6KB smem,
// 2 blocks/SM. smem-staged M + A; tf32 MMA; last block computes stats.
// ---------------------------------------------------------------------------
#define K1_SMEM 110600
#define MST 34   // staged row stride in float4
#define MSTF 136 // staged row stride in floats

__global__ __launch_bounds__(256, 2) void quad_kernel(
    const float* __restrict__ A, const float* __restrict__ mask,
    const float* __restrict__ Wq, const float* __restrict__ Wk,
    const float* __restrict__ bq, const float* __restrict__ bk)
{
    extern __shared__ char smem[];
    float*  sMf   = (float*)smem;
    float4* sM4   = (float4*)smem;
    float*  sAf   = (float*)(smem + 69632);
    float4* sA4   = (float4*)(smem + 69632);
    float*  sPart = (float*)(smem + 104448);
    float*  asum  = (float*)(smem + 108544);
    float*  qs    = (float*)(smem + 109056);
    float*  sMask = (float*)(smem + 109568);
    int*    sLoc  = (int*)(smem + 109824);
    float*  sS    = (float*)(smem + 110080);
    int*    sCnt  = (int*)(smem + 110592);
    int*    sLast = (int*)(smem + 110596);

    const int warp = threadIdx.x >> 5, lane = threadIdx.x & 31, tid = threadIdx.x;
    const int b = blockIdx.x >> 3;
    const int c = blockIdx.x & 7;
    const int r0 = c * 64;
    const size_t base = (size_t)b * NN;
    const float4* A4 = (const float4*)A;
    const float4* gM4 = (const float4*)g_M;
    const float4* Wq4 = (const float4*)Wq;
    const float4* Wk4 = (const float4*)Wk;

    // ---- stage M, A rows, mask; init sLoc ----
#pragma unroll 4
    for (int idx = tid; idx < 4096; idx += 256)
        sM4[(idx >> 5) * MST + (idx & 31)] = gM4[idx];
#pragma unroll 2
    for (int idx = tid; idx < 2048; idx += 256) {
        int r = idx >> 5, col = idx & 31;
        sA4[r * MST + col] = A4[(base + r0 + r) * 32 + col];
    }
    if (tid < 64) { sMask[tid] = mask[base + r0 + tid]; sLoc[tid] = -1; }
    __syncthreads();

    // ---- masked partial sums (warp w -> rows w*8..w*8+7) ----
    {
        float4 acc = make_float4(0.f, 0.f, 0.f, 0.f);
#pragma unroll
        for (int j = 0; j < 8; j++) {
            int r = warp * 8 + j;
            float m = sMask[r];
            float4 a = sA4[r * MST + lane];
            acc.x = fmaf(m, a.x, acc.x);
            acc.y = fmaf(m, a.y, acc.y);
            acc.z = fmaf(m, a.z, acc.z);
            acc.w = fmaf(m, a.w, acc.w);
        }
        ((float4*)(sPart + warp * 128))[lane] = acc;
    }

    // ---- chunk compaction (warp 0) ----
    if (warp == 0) {
        float m0 = sMask[lane];
        float m1 = sMask[32 + lane];
        unsigned b0 = __ballot_sync(0xffffffffu, m0 > 0.f);
        unsigned b1 = __ballot_sync(0xffffffffu, m1 > 0.f);
        int c0 = __popc(b0);
        int pre0 = __popc(b0 & ((1u << lane) - 1u));
        int pre1 = __popc(b1 & ((1u << lane) - 1u));
        if (m0 > 0.f) sLoc[pre0] = lane;
        if (m1 > 0.f) sLoc[c0 + pre1] = 32 + lane;
        if (lane == 0) {
            int tot = c0 + __popc(b1);
            g_ccnt[b * 8 + c] = tot;
            *sCnt = tot;
        }
    }
    __syncthreads();

    // ---- reduce partials to global ----
    if (tid < 128) {
        float s = 0.f;
#pragma unroll
        for (int w = 0; w < 8; w++) s += sPart[w * 128 + tid];
        g_part[((size_t)b * 8 + c) * 128 + tid] = s;
    }

    // ---- tf32 tensor-core quadratic form (single MMA per tile) ----
    {
        const int cnt = *sCnt;
        const int rg = warp & 3;
        const int dh = warp >> 2;
        const int g  = lane >> 2;
        const int tg = lane & 3;

        if (rg * 16 < cnt) {
            const int slot0 = rg * 16 + g;
            const int slot1 = slot0 + 8;
            const int loc0 = sLoc[slot0];
            const int loc1 = sLoc[slot1];
            const int l0 = (loc0 >= 0) ? loc0 : 0;
            const int l1 = (loc1 >= 0) ? loc1 : 0;

            float acc[8][4];
#pragma unroll
            for (int t = 0; t < 8; t++)
#pragma unroll
                for (int j = 0; j < 4; j++) acc[t][j] = 0.f;

#pragma unroll
            for (int k = 0; k < 16; k++) {
                const int e0 = k * 8;
                uint32_t ah[4];
                ah[0] = tf32_bits(sAf[l0 * MSTF + e0 + tg]);
                ah[1] = tf32_bits(sAf[l1 * MSTF + e0 + tg]);
                ah[2] = tf32_bits(sAf[l0 * MSTF + e0 + tg + 4]);
                ah[3] = tf32_bits(sAf[l1 * MSTF + e0 + tg + 4]);
#pragma unroll
                for (int t = 0; t < 8; t++) {
                    const int n0 = dh * 64 + t * 8;
                    uint32_t b0 = __float_as_uint(sMf[(e0 + tg) * MSTF + n0 + g]);
                    uint32_t b1 = __float_as_uint(sMf[(e0 + tg + 4) * MSTF + n0 + g]);
                    mma_tf32(acc[t], ah, b0, b1);
                }
            }

            float p0 = 0.f, p1 = 0.f;
#pragma unroll
            for (int t = 0; t < 8; t++) {
                const int col = dh * 64 + t * 8 + tg * 2;
                float2 x0 = *(const float2*)&sAf[l0 * MSTF + col];
                float2 x1 = *(const float2*)&sAf[l1 * MSTF + col];
                p0 += acc[t][0] * x0.x + acc[t][1] * x0.y;
                p1 += acc[t][2] * x1.x + acc[t][3] * x1.y;
            }
            p0 += __shfl_xor_sync(0xffffffffu, p0, 1);
            p0 += __shfl_xor_sync(0xffffffffu, p0, 2);
            p1 += __shfl_xor_sync(0xffffffffu, p1, 1);
            p1 += __shfl_xor_sync(0xffffffffu, p1, 2);
            if (tg == 0) {
                sS[dh * 64 + slot0] = p0;
                sS[dh * 64 + slot1] = p1;
            }
        }
    }
    __syncthreads();

    if (tid < 64) {
        int loc = sLoc[tid];
        if (loc >= 0) g_s[base + r0 + loc] = sS[tid] + sS[64 + tid];
    }

    // ---- last-block-done: per-batch stats ----
    __threadfence();
    __syncthreads();
    if (tid == 0) {
        int old = atomicAdd(&g_arrive[b], 1);
        *sLast = (old == 7) ? 1 : 0;
    }
    __syncthreads();
    if (*sLast) {
        int cnt = 0;
#pragma unroll
        for (int cc = 0; cc < 8; cc++) cnt += g_ccnt[b * 8 + cc];

        if (tid < 128) {
            float s = 0.f;
#pragma unroll
            for (int cc = 0; cc < 8; cc++) s += g_part[((size_t)b * 8 + cc) * 128 + tid];
            asum[tid] = s;
        }
        __syncthreads();

        if (tid < 128) {
            float q = (float)cnt * bq[tid];
#pragma unroll 8
            for (int d = 0; d < DD; d++) q = fmaf(asum[d], Wq[d * MM + tid], q);
            qs[tid] = q;
        }
        __syncthreads();

        if (warp == 0) {
            float cv = 0.f;
            for (int m = lane; m < MM; m += 32) cv = fmaf(bk[m], qs[m] - bq[m], cv);
            cv = warp_sum(cv);
            if (lane == 0) g_C[b] = cv;
        }

        {
            float4 qs4 = ((const float4*)qs)[lane];
            float4 bk4 = ((const float4*)bk)[lane];
#pragma unroll
            for (int d = warp; d < DD; d += 8) {
                float p = dot4(Wk4[d * 32 + lane], qs4) - dot4(Wq4[d * 32 + lane], bk4);
                p = warp_sum(p);
                if (lane == 0) g_G[b * DD + d] = p;
            }
        }
        if (tid == 0) atomicExch(&g_arrive[b], 0);
    }
}

// ---------------------------------------------------------------------------
// K2 v3: per batch (1024 threads). Phases:
//   1) lin pass + masked agg + ss accumulation (fused)
//   2) exp + sum (fixed shift 1: |score|<=1 since sum(score^2)=1 -> no max pass)
//   3) attn store + wsum accumulate (fused)
//   4) context
// ---------------------------------------------------------------------------
__global__ __launch_bounds__(1024) void softmax_ctx_kernel(
    const float* __restrict__ A, const float* __restrict__ mask,
    const float* __restrict__ Wk, const float* __restrict__ bk,
    float* __restrict__ out)
{
    const int b = blockIdx.x;
    const int warp = threadIdx.x >> 5, lane = threadIdx.x & 31, tid = threadIdx.x;
    const size_t base = (size_t)b * NN;
    const float4* A4 = (const float4*)A;

    __shared__ float sc[NN];
    __shared__ float sMaskS[NN];
    __shared__ float sRed[32];
    __shared__ float sW[32][128];
    __shared__ float wsum[128];

    // phase 1: agg (lin - s + C, masked) + sum of squares, fused
    {
        float4 G4 = ((const float4*)(g_G + b * DD))[lane];
        const float C = g_C[b];
        float ssacc = 0.f;
#pragma unroll
        for (int i = warp; i < NN; i += 32) {
            float m = mask[base + i];
            float4 a = A4[(base + i) * 32 + lane];
            float lin = dot4(a, G4);
            lin = warp_sum(lin);
            if (lane == 0) {
                float v = (m > 0.f) ? (lin - g_s[base + i] + C) : 0.f;
                sc[i] = v;
                sMaskS[i] = m;
                ssacc = fmaf(v, v, ssacc);
            }
        }
        if (lane == 0) sRed[warp] = ssacc;
    }
    __syncthreads();
    float tot = 0.f;
#pragma unroll
    for (int w = 0; w < 32; w++) tot += sRed[w];
    float inv = rsqrtf(tot);

    // phase 2: exp (shift by 1; scores in [-1,1]) + sum
    float es = 0.f;
    for (int i = tid; i < NN; i += 1024) {
        float m = sMaskS[i];
        float e = (m > 0.f) ? __expf(sc[i] * inv - 1.0f) : 0.f;
        sc[i] = e;
        es += e;
    }
    es = warp_sum(es);
    __syncthreads();
    if (lane == 0) sRed[warp] = es;
    __syncthreads();
    float S = 0.f;
#pragma unroll
    for (int w = 0; w < 32; w++) S += sRed[w];
    float invS = 1.0f / S;

    // phase 3: attn store + wsum accumulate, fused (warp per row)
    float4 wacc = make_float4(0.f, 0.f, 0.f, 0.f);
#pragma unroll
    for (int i = warp; i < NN; i += 32) {
        float at = sc[i] * invS;
        if (lane == 0) out[base + i] = at;
        float4 a = A4[(base + i) * 32 + lane];
        wacc.x = fmaf(at, a.x, wacc.x);
        wacc.y = fmaf(at, a.y, wacc.y);
        wacc.z = fmaf(at, a.z, wacc.z);
        wacc.w = fmaf(at, a.w, wacc.w);
    }
    ((float4*)sW[warp])[lane] = wacc;
    __syncthreads();
    if (tid < 128) {
        float s = 0.f;
#pragma unroll
        for (int w = 0; w < 32; w++) s += sW[w][tid];
        wsum[tid] = s;
    }
    __syncthreads();

    // phase 4: context[m] = sum_d wsum[d]*Wk[d,m] + bk[m]
    if (tid < 128) {
        float c = bk[tid];
#pragma unroll 8
        for (int d = 0; d < DD; d++) c = fmaf(wsum[d], Wk[d * MM + tid], c);
        out[(size_t)BB * NN + (size_t)b * MM + tid] = c;
    }
}

extern "C" void kernel_launch(void* const* d_in, const int* in_sizes, int n_in,
                              void* d_out, int out_size)
{
    const float* A    = (const float*)d_in[0];
    const float* mask = (const float*)d_in[1];
    const float* Wq   = (const float*)d_in[2];
    const float* bq   = (const float*)d_in[3];
    const float* Wk   = (const float*)d_in[4];
    const float* bk   = (const float*)d_in[5];
    float* out = (float*)d_out;

    cudaFuncSetAttribute(quad_kernel,
                         cudaFuncAttributeMaxDynamicSharedMemorySize, K1_SMEM);

    mcol_kernel<<<128, 256>>>(Wq, Wk);
    quad_kernel<<<BB * 8, 256, K1_SMEM>>>(A, mask, Wq, Wk, bq, bk);
    softmax_ctx_kernel<<<BB, 1024>>>(A, mask, Wk, bk, out);
}